// round 6
// baseline (speedup 1.0000x reference)
#include <cuda_runtime.h>
#include <cstdint>
#include <math.h>

// ---------------- problem constants ----------------
#define B_SZ 4
#define T_SZ 2048
#define D_SZ 1024
#define M_SZ (B_SZ * T_SZ)
#define MD   ((long)M_SZ * D_SZ)
#define DD   ((long)D_SZ * D_SZ)
#define ETA_C 0.1f
#define LCA_GEMM_ITERS 9   // iteration 1 is elementwise (a=0, v=0)

// ---------------- scratch (device globals; no allocation) ----------------
__device__ float g_u3[3 * M_SZ * D_SZ];      // u_q, u_k, v (fp32; z-indexed)
__device__ float g_vt[M_SZ * D_SZ];          // V^T per batch [B][D][T] (tf32-rounded)
__device__ float g_vs[2 * M_SZ * D_SZ];      // LCA v-state (fp32)
__device__ float g_ab[2][2 * M_SZ * D_SZ];   // LCA codes ping-pong x (q,k) (tf32-rounded)
__device__ float g_G2[2 * D_SZ * D_SZ];      // sym zero-diag Gq,Gk (tf32-rounded)
__device__ float g_S[(size_t)B_SZ * T_SZ * T_SZ];   // scores / probs
__device__ float g_o[M_SZ * D_SZ];           // attention out (tf32-rounded)
__device__ float g_xr[M_SZ * D_SZ];          // x rounded
__device__ float g_wqkvr[3 * D_SZ * D_SZ];   // W_qkv rounded
__device__ float g_woutr[D_SZ * D_SZ];       // W_out rounded

// ---------------- helpers ----------------
__device__ __forceinline__ uint32_t smem_u32(const void* p) {
    uint32_t a;
    asm("{ .reg .u64 t; cvta.to.shared.u64 t, %1; cvt.u32.u64 %0, t; }" : "=r"(a) : "l"(p));
    return a;
}
__device__ __forceinline__ void cp_async16(uint32_t dst, const void* src) {
    asm volatile("cp.async.cg.shared.global [%0], [%1], 16;" :: "r"(dst), "l"(src));
}
#define CP_COMMIT() asm volatile("cp.async.commit_group;" ::: "memory")
#define CP_WAIT1()  asm volatile("cp.async.wait_group 1;" ::: "memory")
#define CP_WAIT0()  asm volatile("cp.async.wait_group 0;" ::: "memory")

__device__ __forceinline__ uint32_t f2tf32(float f) {
    uint32_t r;
    asm("cvt.rna.tf32.f32 %0, %1;" : "=r"(r) : "f"(f));
    return r;
}
__device__ __forceinline__ float rtf(float f) { return __uint_as_float(f2tf32(f)); }

__device__ __forceinline__ void mma_tf32(float* c, const uint32_t* a, const uint32_t* b) {
    asm volatile(
        "mma.sync.aligned.m16n8k8.row.col.f32.tf32.tf32.f32 "
        "{%0,%1,%2,%3}, {%4,%5,%6,%7}, {%8,%9}, {%0,%1,%2,%3};"
        : "+f"(c[0]), "+f"(c[1]), "+f"(c[2]), "+f"(c[3])
        : "r"(a[0]), "r"(a[1]), "r"(a[2]), "r"(a[3]), "r"(b[0]), "r"(b[1]));
}

// ---------------- GEMM (NT): C[m,n] = alpha * sum_k A[m,k]*B[n,k] ----------------
// Inputs pre-rounded to tf32 by producers; inner loop is LDS.128 + MMA only.
// Implicit k-relabeling: within smem cols [16d,16d+16) of a 32-K chunk, lane lc
// owns cols 16d+4lc+{0,1,2,3} = (even-octet k=lc, even k=lc+4, odd k=lc, odd k=lc+4).
// Identity cp.async staging; A and B use the same labeling -> exact GEMM.
#define MODE_PLAIN 0
#define MODE_LCA   1   // fused LCA prox epilogue (z: 0=q, 1=k); writes tf32-rounded a
#define MODE_SCORE 2   // skip tiles fully above the causal diagonal
#define MODE_PV    3   // causal K-limit; writes tf32-rounded C

#define BK   32
#define STRD 48                       // floats per smem row (192B; LDS.128 conflict-free)
#define TILE_SM (128 * STRD)
#define GSMEM_BYTES (4 * TILE_SM * 4) // 2 A + 2 B buffers = 98304 B

template <int MODE>
__global__ void __launch_bounds__(256, 2)
mm_tf32(const float* __restrict__ A, const float* __restrict__ Bm, float* __restrict__ C,
        int K, int ldA, int ldB, int ldC, float alpha,
        long sA, long sB, long sC,
        const float* __restrict__ U, float* __restrict__ Vst,
        const float* __restrict__ llq, const float* __restrict__ llk)
{
    const int r0 = blockIdx.y * 128;
    const int c0 = blockIdx.x * 128;
    if (MODE == MODE_SCORE && c0 >= r0 + 128) return;   // fully masked tile

    const long bz = blockIdx.z;
    A  += bz * sA;
    Bm += bz * sB;
    C  += bz * sC;

    extern __shared__ uint32_t sm[];
    uint32_t* Asb[2] = { sm,               sm + TILE_SM };
    uint32_t* Bsb[2] = { sm + 2 * TILE_SM, sm + 3 * TILE_SM };

    const int tid  = threadIdx.x;
    const int lane = tid & 31;
    const int wid  = tid >> 5;
    const int wm   = (wid >> 2) * 64;
    const int wn   = (wid & 3) * 32;
    const int lr   = lane >> 2;         // 0..7
    const int lc   = lane & 3;          // 0..3

    const int kmax = (MODE == MODE_PV) ? min(K, r0 + 128) : K;
    const int nch  = kmax / BK;

    float acc[4][4][4];
#pragma unroll
    for (int i = 0; i < 4; i++)
#pragma unroll
        for (int j = 0; j < 4; j++)
#pragma unroll
            for (int e = 0; e < 4; e++) acc[i][j][e] = 0.f;

    auto issue = [&](int c) {
        const int buf = c & 1;
        const float* Ac = A  + (long)r0 * ldA + c * BK;
        const float* Bc = Bm + (long)c0 * ldB + c * BK;
        const uint32_t ab = smem_u32(Asb[buf]);
        const uint32_t bb = smem_u32(Bsb[buf]);
#pragma unroll
        for (int i = 0; i < 4; i++) {
            const int idx = tid + i * 256;
            const int row = idx >> 3, c4 = idx & 7;
            cp_async16(ab + (uint32_t)(row * STRD + c4 * 4) * 4, Ac + (long)row * ldA + c4 * 4);
            cp_async16(bb + (uint32_t)(row * STRD + c4 * 4) * 4, Bc + (long)row * ldB + c4 * 4);
        }
        CP_COMMIT();
    };

    issue(0);
    for (int c = 0; c < nch; c++) {
        if (c + 1 < nch) { issue(c + 1); CP_WAIT1(); }
        else             { CP_WAIT0(); }
        __syncthreads();

        const uint32_t* Ab = Asb[c & 1];
        const uint32_t* Bb = Bsb[c & 1];
#pragma unroll
        for (int d = 0; d < 2; d++) {            // two 16-col groups (2 octets each)
            const int goff = d * 16 + lc * 4;
            uint4 alo[4], ahi[4];
#pragma unroll
            for (int mt = 0; mt < 4; mt++) {
                const uint32_t* p = Ab + (wm + mt * 16 + lr) * STRD + goff;
                alo[mt] = *(const uint4*)p;             // row lr:   (a0e, a2e, a0o, a2o)
                ahi[mt] = *(const uint4*)(p + 8 * STRD);// row lr+8: (a1e, a3e, a1o, a3o)
            }
#pragma unroll
            for (int nt = 0; nt < 4; nt++) {
                const uint4 bv = *(const uint4*)(Bb + (wn + nt * 8 + lr) * STRD + goff);
                const uint32_t be[2] = { bv.x, bv.y };  // even octet b0,b1
                const uint32_t bo[2] = { bv.z, bv.w };  // odd  octet b0,b1
#pragma unroll
                for (int mt = 0; mt < 4; mt++) {
                    const uint32_t ae[4] = { alo[mt].x, ahi[mt].x, alo[mt].y, ahi[mt].y };
                    mma_tf32(acc[mt][nt], ae, be);
                    const uint32_t ao[4] = { alo[mt].z, ahi[mt].z, alo[mt].w, ahi[mt].w };
                    mma_tf32(acc[mt][nt], ao, bo);
                }
            }
        }
        __syncthreads();
    }

    // ---------------- epilogue ----------------
    const float lam = (MODE == MODE_LCA) ? expf(bz == 0 ? *llq : *llk) : 0.f;
#pragma unroll
    for (int mt = 0; mt < 4; mt++) {
#pragma unroll
        for (int h = 0; h < 2; h++) {
            const int row = r0 + wm + mt * 16 + lr + h * 8;
#pragma unroll
            for (int nt = 0; nt < 4; nt++) {
                const int col = c0 + wn + nt * 8 + lc * 2;
                const long idx = (long)row * ldC + col;
                float x0 = acc[mt][nt][h * 2 + 0];
                float x1 = acc[mt][nt][h * 2 + 1];
                if (MODE == MODE_LCA) {
                    float2 u2 = *(const float2*)(U + bz * sC + idx);
                    float2 v2 = *(const float2*)(Vst + bz * sC + idx);
                    float2 vn, o2;
                    vn.x = v2.x + ETA_C * (u2.x - v2.x - x0);
                    vn.y = v2.y + ETA_C * (u2.y - v2.y - x1);
                    *(float2*)(Vst + bz * sC + idx) = vn;
                    float s;
                    s = fabsf(vn.x) - lam; o2.x = (s > 0.f) ? rtf(copysignf(s, vn.x)) : 0.f;
                    s = fabsf(vn.y) - lam; o2.y = (s > 0.f) ? rtf(copysignf(s, vn.y)) : 0.f;
                    *(float2*)(C + idx) = o2;
                } else if (MODE == MODE_PV) {
                    *(float2*)(C + idx) = make_float2(rtf(x0), rtf(x1));   // feeds final GEMM
                } else {
                    *(float2*)(C + idx) = make_float2(alpha * x0, alpha * x1);
                }
            }
        }
    }
}

// ---------------- small kernels ----------------
__global__ void round_copy(const float* __restrict__ in, float* __restrict__ out)
{
    const long i = ((long)blockIdx.x * blockDim.x + threadIdx.x) * 4;
    float4 v = *(const float4*)(in + i);
    v.x = rtf(v.x); v.y = rtf(v.y); v.z = rtf(v.z); v.w = rtf(v.w);
    *(float4*)(out + i) = v;
}

__global__ void symzero(const float* __restrict__ G, float* __restrict__ Gs)
{
    const long idx = (long)blockIdx.x * blockDim.x + threadIdx.x;
    if (idx >= DD) return;
    const int i = (int)(idx / D_SZ), j = (int)(idx % D_SZ);
    Gs[idx] = (i == j) ? 0.f : rtf(0.5f * (G[idx] + G[(long)j * D_SZ + i]));
}

__global__ void lca_init(const float* __restrict__ U, float* __restrict__ Vst,
                         float* __restrict__ Aout,
                         const float* __restrict__ llq, const float* __restrict__ llk)
{
    const long idx = (long)blockIdx.x * blockDim.x + threadIdx.x;
    const float lam = expf(idx < MD ? *llq : *llk);
    const float vn = ETA_C * U[idx];
    Vst[idx] = vn;
    const float s = fabsf(vn) - lam;
    Aout[idx] = (s > 0.f) ? rtf(copysignf(s, vn)) : 0.f;
}

// V [B][T][D] -> Vt [B][D][T], tf32-rounded
__global__ void transpose_bt(const float* __restrict__ in, float* __restrict__ out)
{
    __shared__ float t[32][33];
    const int b = blockIdx.z;
    const int t0 = blockIdx.x * 32, d0 = blockIdx.y * 32;
    in  += (long)b * T_SZ * D_SZ;
    out += (long)b * T_SZ * D_SZ;
    const int x = threadIdx.x, y = threadIdx.y;
#pragma unroll
    for (int i = 0; i < 32; i += 8)
        t[y + i][x] = in[(long)(t0 + y + i) * D_SZ + d0 + x];
    __syncthreads();
#pragma unroll
    for (int i = 0; i < 32; i += 8)
        out[(long)(d0 + y + i) * T_SZ + t0 + x] = rtf(t[x][y + i]);
}

__global__ void softmax_causal(float* __restrict__ S)
{
    const int i = blockIdx.x;
    const int b = blockIdx.y;
    float* row = S + ((long)b * T_SZ + i) * T_SZ;
    const int tid = threadIdx.x;
    const int n = i + 1;
    __shared__ float red[256];

    float mx = -INFINITY;
    for (int j = tid; j < n; j += 256) mx = fmaxf(mx, row[j]);
    red[tid] = mx;
    __syncthreads();
    for (int s = 128; s > 0; s >>= 1) {
        if (tid < s) red[tid] = fmaxf(red[tid], red[tid + s]);
        __syncthreads();
    }
    mx = red[0];
    __syncthreads();

    float sum = 0.f;
    for (int j = tid; j < n; j += 256) {
        float e = expf(row[j] - mx);
        row[j] = e;
        sum += e;
    }
    red[tid] = sum;
    __syncthreads();
    for (int s = 128; s > 0; s >>= 1) {
        if (tid < s) red[tid] += red[tid + s];
        __syncthreads();
    }
    const float inv = 1.f / red[0];
    for (int j = tid; j < n; j += 256) row[j] = rtf(row[j] * inv);   // feeds PV GEMM
    for (int j = n + tid; j < T_SZ; j += 256) row[j] = 0.f;
}

// ---------------- launch ----------------
extern "C" void kernel_launch(void* const* d_in, const int* in_sizes, int n_in,
                              void* d_out, int out_size)
{
    const float* x        = (const float*)d_in[0];
    const float* W_qkv    = (const float*)d_in[1];
    const float* W_out    = (const float*)d_in[2];
    const float* Gq_raw   = (const float*)d_in[3];
    const float* loglam_q = (const float*)d_in[4];
    const float* Gk_raw   = (const float*)d_in[5];
    const float* loglam_k = (const float*)d_in[6];
    float* out = (float*)d_out;
    (void)in_sizes; (void)n_in; (void)out_size;

    float *u3, *vt, *vs, *abb, *G2, *S, *o, *xr, *wqr, *wor;
    cudaGetSymbolAddress((void**)&u3,  g_u3);
    cudaGetSymbolAddress((void**)&vt,  g_vt);
    cudaGetSymbolAddress((void**)&vs,  g_vs);
    cudaGetSymbolAddress((void**)&abb, g_ab);
    cudaGetSymbolAddress((void**)&G2,  g_G2);
    cudaGetSymbolAddress((void**)&S,   g_S);
    cudaGetSymbolAddress((void**)&o,   g_o);
    cudaGetSymbolAddress((void**)&xr,  g_xr);
    cudaGetSymbolAddress((void**)&wqr, g_wqkvr);
    cudaGetSymbolAddress((void**)&wor, g_woutr);

    cudaFuncSetAttribute(mm_tf32<MODE_PLAIN>, cudaFuncAttributeMaxDynamicSharedMemorySize, GSMEM_BYTES);
    cudaFuncSetAttribute(mm_tf32<MODE_LCA>,   cudaFuncAttributeMaxDynamicSharedMemorySize, GSMEM_BYTES);
    cudaFuncSetAttribute(mm_tf32<MODE_SCORE>, cudaFuncAttributeMaxDynamicSharedMemorySize, GSMEM_BYTES);
    cudaFuncSetAttribute(mm_tf32<MODE_PV>,    cudaFuncAttributeMaxDynamicSharedMemorySize, GSMEM_BYTES);

    float* ab[2] = { abb, abb + 2 * MD };
    float* vvv = u3 + 2 * MD;

    const dim3 thr(256);
    const long TD = (long)T_SZ * D_SZ;
    const long TT = (long)T_SZ * T_SZ;

    // 0) pre-round raw GEMM inputs to tf32
    round_copy<<<(unsigned)(MD / 1024), thr>>>(x, xr);
    round_copy<<<(unsigned)(3 * DD / 1024), thr>>>(W_qkv, wqr);
    round_copy<<<(unsigned)(DD / 1024), thr>>>(W_out, wor);

    // 1) symmetrize + zero-diag G (tf32-rounded)
    {
        dim3 g((unsigned)((DD + 255) / 256));
        symzero<<<g, thr>>>(Gq_raw, G2);
        symzero<<<g, thr>>>(Gk_raw, G2 + DD);
    }

    // 2) QKV projections, single launch (z selects W block and output slot); u stays fp32
    {
        dim3 g(D_SZ / 128, M_SZ / 128, 3);
        mm_tf32<MODE_PLAIN><<<g, thr, GSMEM_BYTES>>>(xr, wqr, u3, D_SZ, D_SZ, D_SZ, D_SZ, 1.f,
                                                     0, DD, MD, nullptr, nullptr, nullptr, nullptr);
    }

    // 3) transpose V (tf32-rounded)
    {
        dim3 g(T_SZ / 32, D_SZ / 32, B_SZ);
        transpose_bt<<<g, dim3(32, 8)>>>(vvv, vt);
    }

    // 4) LCA iteration 1 (elementwise, q+k)
    {
        dim3 g((unsigned)(2 * MD / 256));
        lca_init<<<g, thr>>>(u3, vs, ab[0], loglam_q, loglam_k);
    }

    // 5) LCA iterations 2..10: fused a@G + prox, q+k merged over z
    {
        dim3 g(D_SZ / 128, M_SZ / 128, 2);
        int cur = 0;
        for (int it = 0; it < LCA_GEMM_ITERS; it++) {
            mm_tf32<MODE_LCA><<<g, thr, GSMEM_BYTES>>>(ab[cur], G2, ab[cur ^ 1],
                                                       D_SZ, D_SZ, D_SZ, D_SZ, 1.f,
                                                       MD, DD, MD, u3, vs, loglam_q, loglam_k);
            cur ^= 1;
        }
    }
    float* qf = ab[1];
    float* kf = ab[1] + MD;

    // 6) scores S = q k^T / 32, causal tiles skipped
    {
        dim3 g(T_SZ / 128, T_SZ / 128, B_SZ);
        mm_tf32<MODE_SCORE><<<g, thr, GSMEM_BYTES>>>(qf, kf, S, D_SZ, D_SZ, D_SZ, T_SZ, 0.03125f,
                                                     TD, TD, TT, nullptr, nullptr, nullptr, nullptr);
    }

    // 7) causal softmax (in place; rounds probs, zeroes masked tail)
    {
        dim3 g(T_SZ, B_SZ);
        softmax_causal<<<g, thr>>>(S);
    }

    // 8) o = P @ V (NT against Vt, causal K-limit); o tf32-rounded
    {
        dim3 g(D_SZ / 128, T_SZ / 128, B_SZ);
        mm_tf32<MODE_PV><<<g, thr, GSMEM_BYTES>>>(S, vt, o, T_SZ, T_SZ, T_SZ, D_SZ, 1.f,
                                                  TT, TD, TD, nullptr, nullptr, nullptr, nullptr);
    }

    // 9) out = o @ W_out^T (fp32 output)
    {
        dim3 g(D_SZ / 128, M_SZ / 128, 1);
        mm_tf32<MODE_PLAIN><<<g, thr, GSMEM_BYTES>>>(o, wor, out, D_SZ, D_SZ, D_SZ, D_SZ, 1.f,
                                                     0, 0, 0, nullptr, nullptr, nullptr, nullptr);
    }
}

// round 7
// speedup vs baseline: 1.1190x; 1.1190x over previous
#include <cuda_runtime.h>
#include <cstdint>
#include <math.h>

// ---------------- problem constants ----------------
#define B_SZ 4
#define T_SZ 2048
#define D_SZ 1024
#define M_SZ (B_SZ * T_SZ)
#define MD   ((long)M_SZ * D_SZ)
#define DD   ((long)D_SZ * D_SZ)
#define ETA_C 0.1f
#define LCA_GEMM_ITERS 9   // iteration 1 is elementwise (a=0, v=0)

// ---------------- scratch (device globals; no allocation) ----------------
__device__ float g_u3[3 * M_SZ * D_SZ];      // u_q, u_k, v (fp32; z-indexed)
__device__ float g_vt[M_SZ * D_SZ];          // V^T per batch [B][D][T] (tf32-rounded)
__device__ float g_vs[2 * M_SZ * D_SZ];      // LCA v-state (fp32)
__device__ float g_ab[2][2 * M_SZ * D_SZ];   // LCA codes ping-pong x (q,k) (tf32-rounded)
__device__ float g_G2[2 * D_SZ * D_SZ];      // sym zero-diag Gq,Gk (tf32-rounded)
__device__ float g_S[(size_t)B_SZ * T_SZ * T_SZ];   // scores / probs
__device__ float g_o[M_SZ * D_SZ];           // attention out (tf32-rounded)
__device__ float g_xr[M_SZ * D_SZ];          // x rounded
__device__ float g_wqkvr[3 * D_SZ * D_SZ];   // W_qkv rounded
__device__ float g_woutr[D_SZ * D_SZ];       // W_out rounded

// ---------------- helpers ----------------
__device__ __forceinline__ uint32_t smem_u32(const void* p) {
    uint32_t a;
    asm("{ .reg .u64 t; cvta.to.shared.u64 t, %1; cvt.u32.u64 %0, t; }" : "=r"(a) : "l"(p));
    return a;
}
__device__ __forceinline__ void cp_async16(uint32_t dst, const void* src) {
    asm volatile("cp.async.cg.shared.global [%0], [%1], 16;" :: "r"(dst), "l"(src));
}
#define CP_COMMIT() asm volatile("cp.async.commit_group;" ::: "memory")
#define CP_WAIT1()  asm volatile("cp.async.wait_group 1;" ::: "memory")
#define CP_WAIT0()  asm volatile("cp.async.wait_group 0;" ::: "memory")

__device__ __forceinline__ uint32_t f2tf32(float f) {
    uint32_t r;
    asm("cvt.rna.tf32.f32 %0, %1;" : "=r"(r) : "f"(f));
    return r;
}
__device__ __forceinline__ float rtf(float f) { return __uint_as_float(f2tf32(f)); }

__device__ __forceinline__ void mma_tf32(float* c, const uint32_t* a, const uint32_t* b) {
    asm volatile(
        "mma.sync.aligned.m16n8k8.row.col.f32.tf32.tf32.f32 "
        "{%0,%1,%2,%3}, {%4,%5,%6,%7}, {%8,%9}, {%0,%1,%2,%3};"
        : "+f"(c[0]), "+f"(c[1]), "+f"(c[2]), "+f"(c[3])
        : "r"(a[0]), "r"(a[1]), "r"(a[2]), "r"(a[3]), "r"(b[0]), "r"(b[1]));
}

// ---------------- GEMM (NT): C[m,n] = alpha * sum_k A[m,k]*B[n,k] ----------------
// CTA tile 128x256, 8 warps in 2x4 grid of 64x64 warp tiles (crossbar-traffic
// optimized: 0.172 B/MAC vs 0.25 for 128x128). 3-stage cp.async pipeline with a
// single __syncthreads per chunk. Inputs pre-rounded tf32; k-permuted smem
// layout (mma-k (o,lc)->col 8o+2lc, (o,lc+4)->col 8o+2lc+1) for uint2 loads.
#define MODE_PLAIN 0
#define MODE_LCA   1   // fused LCA prox epilogue (z: 0=q, 1=k); writes tf32-rounded a
#define MODE_SCORE 2   // skip tiles fully above the causal diagonal
#define MODE_PV    3   // causal K-limit; writes tf32-rounded C

#define BM   128
#define BN   256
#define BK   32
#define STRD 40                          // floats per smem row (LDS.64 conflict-free)
#define TILE_A (BM * STRD)               // 5120 floats
#define TILE_B (BN * STRD)               // 10240 floats
#define STAGE_FL (TILE_A + TILE_B)       // 15360 floats
#define NSTAGE 3
#define GSMEM_BYTES (NSTAGE * STAGE_FL * 4)   // 184320 B

template <int MODE>
__global__ void __launch_bounds__(256, 1)
mm_tf32(const float* __restrict__ A, const float* __restrict__ Bm, float* __restrict__ C,
        int K, int ldA, int ldB, int ldC, float alpha,
        long sA, long sB, long sC,
        const float* __restrict__ U, float* __restrict__ Vst,
        const float* __restrict__ llq, const float* __restrict__ llk)
{
    const int r0 = blockIdx.y * BM;
    const int c0 = blockIdx.x * BN;
    if (MODE == MODE_SCORE && c0 >= r0 + BM) return;   // fully masked tile

    const long bz = blockIdx.z;
    A  += bz * sA;
    Bm += bz * sB;
    C  += bz * sC;

    extern __shared__ uint32_t sm[];

    const int tid  = threadIdx.x;
    const int lane = tid & 31;
    const int wid  = tid >> 5;
    const int wm   = (wid >> 2) * 64;   // warp row offset (0 or 64)
    const int wn   = (wid & 3) * 64;    // warp col offset (0,64,128,192)
    const int lr   = lane >> 2;         // 0..7
    const int lc   = lane & 3;          // 0..3

    const int kmax = (MODE == MODE_PV) ? min(K, r0 + BM) : K;
    const int nch  = kmax / BK;         // >= 4 for all uses

    float acc[4][8][4];
#pragma unroll
    for (int i = 0; i < 4; i++)
#pragma unroll
        for (int j = 0; j < 8; j++)
#pragma unroll
            for (int e = 0; e < 4; e++) acc[i][j][e] = 0.f;

    auto issue = [&](int cc) {
        const int stg = cc % NSTAGE;
        const float* Ac = A  + (long)r0 * ldA + cc * BK;
        const float* Bc = Bm + (long)c0 * ldB + cc * BK;
        const uint32_t ab = smem_u32(sm + stg * STAGE_FL);
        const uint32_t bb = ab + TILE_A * 4;
#pragma unroll
        for (int i = 0; i < 4; i++) {            // A: 1024 float4 slots
            const int idx = tid + i * 256;
            const int row = idx >> 3, c4 = idx & 7;
            cp_async16(ab + (uint32_t)(row * STRD + c4 * 4) * 4, Ac + (long)row * ldA + c4 * 4);
        }
#pragma unroll
        for (int i = 0; i < 8; i++) {            // B: 2048 float4 slots
            const int idx = tid + i * 256;
            const int row = idx >> 3, c4 = idx & 7;
            cp_async16(bb + (uint32_t)(row * STRD + c4 * 4) * 4, Bc + (long)row * ldB + c4 * 4);
        }
        CP_COMMIT();
    };

    issue(0);
    issue(1);
    for (int c = 0; c < nch; c++) {
        if (c + 1 < nch) CP_WAIT1(); else CP_WAIT0();
        __syncthreads();                          // single barrier per chunk

        const uint32_t* Ab = sm + (c % NSTAGE) * STAGE_FL;
        const uint32_t* Bb = Ab + TILE_A;
#pragma unroll
        for (int o = 0; o < 4; o++) {
            const int koff = o * 8 + lc * 2;
            uint32_t af[4][4], bf[8][2];
#pragma unroll
            for (int mt = 0; mt < 4; mt++) {
                const uint2 lo = *(const uint2*)(Ab + (wm + mt * 16 + lr) * STRD + koff);
                const uint2 hi = *(const uint2*)(Ab + (wm + mt * 16 + lr + 8) * STRD + koff);
                af[mt][0] = lo.x;  af[mt][2] = lo.y;
                af[mt][1] = hi.x;  af[mt][3] = hi.y;
            }
#pragma unroll
            for (int nt = 0; nt < 8; nt++) {
                const uint2 bv = *(const uint2*)(Bb + (wn + nt * 8 + lr) * STRD + koff);
                bf[nt][0] = bv.x;  bf[nt][1] = bv.y;
            }
#pragma unroll
            for (int mt = 0; mt < 4; mt++)
#pragma unroll
                for (int nt = 0; nt < 8; nt++)
                    mma_tf32(acc[mt][nt], af[mt], bf[nt]);
        }

        if (c + 2 < nch) issue(c + 2);            // safe: all warps passed sync(c)
    }

    // ---------------- epilogue ----------------
    const float lam = (MODE == MODE_LCA) ? expf(bz == 0 ? *llq : *llk) : 0.f;
#pragma unroll
    for (int mt = 0; mt < 4; mt++) {
#pragma unroll
        for (int h = 0; h < 2; h++) {
            const int row = r0 + wm + mt * 16 + lr + h * 8;
#pragma unroll
            for (int nt = 0; nt < 8; nt++) {
                const int col = c0 + wn + nt * 8 + lc * 2;
                const long idx = (long)row * ldC + col;
                float x0 = acc[mt][nt][h * 2 + 0];
                float x1 = acc[mt][nt][h * 2 + 1];
                if (MODE == MODE_LCA) {
                    float2 u2 = *(const float2*)(U + bz * sC + idx);
                    float2 v2 = *(const float2*)(Vst + bz * sC + idx);
                    float2 vn, o2;
                    vn.x = v2.x + ETA_C * (u2.x - v2.x - x0);
                    vn.y = v2.y + ETA_C * (u2.y - v2.y - x1);
                    *(float2*)(Vst + bz * sC + idx) = vn;
                    float s;
                    s = fabsf(vn.x) - lam; o2.x = (s > 0.f) ? rtf(copysignf(s, vn.x)) : 0.f;
                    s = fabsf(vn.y) - lam; o2.y = (s > 0.f) ? rtf(copysignf(s, vn.y)) : 0.f;
                    *(float2*)(C + idx) = o2;
                } else if (MODE == MODE_PV) {
                    *(float2*)(C + idx) = make_float2(rtf(x0), rtf(x1));   // feeds final GEMM
                } else {
                    *(float2*)(C + idx) = make_float2(alpha * x0, alpha * x1);
                }
            }
        }
    }
}

// ---------------- small kernels ----------------
__global__ void round_copy(const float* __restrict__ in, float* __restrict__ out)
{
    const long i = ((long)blockIdx.x * blockDim.x + threadIdx.x) * 4;
    float4 v = *(const float4*)(in + i);
    v.x = rtf(v.x); v.y = rtf(v.y); v.z = rtf(v.z); v.w = rtf(v.w);
    *(float4*)(out + i) = v;
}

__global__ void symzero(const float* __restrict__ G, float* __restrict__ Gs)
{
    const long idx = (long)blockIdx.x * blockDim.x + threadIdx.x;
    if (idx >= DD) return;
    const int i = (int)(idx / D_SZ), j = (int)(idx % D_SZ);
    Gs[idx] = (i == j) ? 0.f : rtf(0.5f * (G[idx] + G[(long)j * D_SZ + i]));
}

__global__ void lca_init(const float* __restrict__ U, float* __restrict__ Vst,
                         float* __restrict__ Aout,
                         const float* __restrict__ llq, const float* __restrict__ llk)
{
    const long idx = (long)blockIdx.x * blockDim.x + threadIdx.x;
    const float lam = expf(idx < MD ? *llq : *llk);
    const float vn = ETA_C * U[idx];
    Vst[idx] = vn;
    const float s = fabsf(vn) - lam;
    Aout[idx] = (s > 0.f) ? rtf(copysignf(s, vn)) : 0.f;
}

// V [B][T][D] -> Vt [B][D][T], tf32-rounded
__global__ void transpose_bt(const float* __restrict__ in, float* __restrict__ out)
{
    __shared__ float t[32][33];
    const int b = blockIdx.z;
    const int t0 = blockIdx.x * 32, d0 = blockIdx.y * 32;
    in  += (long)b * T_SZ * D_SZ;
    out += (long)b * T_SZ * D_SZ;
    const int x = threadIdx.x, y = threadIdx.y;
#pragma unroll
    for (int i = 0; i < 32; i += 8)
        t[y + i][x] = in[(long)(t0 + y + i) * D_SZ + d0 + x];
    __syncthreads();
#pragma unroll
    for (int i = 0; i < 32; i += 8)
        out[(long)(d0 + y + i) * T_SZ + t0 + x] = rtf(t[x][y + i]);
}

__global__ void softmax_causal(float* __restrict__ S)
{
    const int i = blockIdx.x;
    const int b = blockIdx.y;
    float* row = S + ((long)b * T_SZ + i) * T_SZ;
    const int tid = threadIdx.x;
    const int n = i + 1;
    __shared__ float red[256];

    float mx = -INFINITY;
    for (int j = tid; j < n; j += 256) mx = fmaxf(mx, row[j]);
    red[tid] = mx;
    __syncthreads();
    for (int s = 128; s > 0; s >>= 1) {
        if (tid < s) red[tid] = fmaxf(red[tid], red[tid + s]);
        __syncthreads();
    }
    mx = red[0];
    __syncthreads();

    float sum = 0.f;
    for (int j = tid; j < n; j += 256) {
        float e = expf(row[j] - mx);
        row[j] = e;
        sum += e;
    }
    red[tid] = sum;
    __syncthreads();
    for (int s = 128; s > 0; s >>= 1) {
        if (tid < s) red[tid] += red[tid + s];
        __syncthreads();
    }
    const float inv = 1.f / red[0];
    for (int j = tid; j < n; j += 256) row[j] = rtf(row[j] * inv);   // feeds PV GEMM
    for (int j = n + tid; j < T_SZ; j += 256) row[j] = 0.f;
}

// ---------------- launch ----------------
extern "C" void kernel_launch(void* const* d_in, const int* in_sizes, int n_in,
                              void* d_out, int out_size)
{
    const float* x        = (const float*)d_in[0];
    const float* W_qkv    = (const float*)d_in[1];
    const float* W_out    = (const float*)d_in[2];
    const float* Gq_raw   = (const float*)d_in[3];
    const float* loglam_q = (const float*)d_in[4];
    const float* Gk_raw   = (const float*)d_in[5];
    const float* loglam_k = (const float*)d_in[6];
    float* out = (float*)d_out;
    (void)in_sizes; (void)n_in; (void)out_size;

    float *u3, *vt, *vs, *abb, *G2, *S, *o, *xr, *wqr, *wor;
    cudaGetSymbolAddress((void**)&u3,  g_u3);
    cudaGetSymbolAddress((void**)&vt,  g_vt);
    cudaGetSymbolAddress((void**)&vs,  g_vs);
    cudaGetSymbolAddress((void**)&abb, g_ab);
    cudaGetSymbolAddress((void**)&G2,  g_G2);
    cudaGetSymbolAddress((void**)&S,   g_S);
    cudaGetSymbolAddress((void**)&o,   g_o);
    cudaGetSymbolAddress((void**)&xr,  g_xr);
    cudaGetSymbolAddress((void**)&wqr, g_wqkvr);
    cudaGetSymbolAddress((void**)&wor, g_woutr);

    cudaFuncSetAttribute(mm_tf32<MODE_PLAIN>, cudaFuncAttributeMaxDynamicSharedMemorySize, GSMEM_BYTES);
    cudaFuncSetAttribute(mm_tf32<MODE_LCA>,   cudaFuncAttributeMaxDynamicSharedMemorySize, GSMEM_BYTES);
    cudaFuncSetAttribute(mm_tf32<MODE_SCORE>, cudaFuncAttributeMaxDynamicSharedMemorySize, GSMEM_BYTES);
    cudaFuncSetAttribute(mm_tf32<MODE_PV>,    cudaFuncAttributeMaxDynamicSharedMemorySize, GSMEM_BYTES);

    float* ab[2] = { abb, abb + 2 * MD };
    float* vvv = u3 + 2 * MD;

    const dim3 thr(256);
    const long TD = (long)T_SZ * D_SZ;
    const long TT = (long)T_SZ * T_SZ;

    // 0) pre-round raw GEMM inputs to tf32
    round_copy<<<(unsigned)(MD / 1024), thr>>>(x, xr);
    round_copy<<<(unsigned)(3 * DD / 1024), thr>>>(W_qkv, wqr);
    round_copy<<<(unsigned)(DD / 1024), thr>>>(W_out, wor);

    // 1) symmetrize + zero-diag G (tf32-rounded)
    {
        dim3 g((unsigned)((DD + 255) / 256));
        symzero<<<g, thr>>>(Gq_raw, G2);
        symzero<<<g, thr>>>(Gk_raw, G2 + DD);
    }

    // 2) QKV projections, single launch; u stays fp32
    {
        dim3 g(D_SZ / BN, M_SZ / BM, 3);
        mm_tf32<MODE_PLAIN><<<g, thr, GSMEM_BYTES>>>(xr, wqr, u3, D_SZ, D_SZ, D_SZ, D_SZ, 1.f,
                                                     0, DD, MD, nullptr, nullptr, nullptr, nullptr);
    }

    // 3) transpose V (tf32-rounded)
    {
        dim3 g(T_SZ / 32, D_SZ / 32, B_SZ);
        transpose_bt<<<g, dim3(32, 8)>>>(vvv, vt);
    }

    // 4) LCA iteration 1 (elementwise, q+k)
    {
        dim3 g((unsigned)(2 * MD / 256));
        lca_init<<<g, thr>>>(u3, vs, ab[0], loglam_q, loglam_k);
    }

    // 5) LCA iterations 2..10: fused a@G + prox, q+k merged over z
    {
        dim3 g(D_SZ / BN, M_SZ / BM, 2);
        int cur = 0;
        for (int it = 0; it < LCA_GEMM_ITERS; it++) {
            mm_tf32<MODE_LCA><<<g, thr, GSMEM_BYTES>>>(ab[cur], G2, ab[cur ^ 1],
                                                       D_SZ, D_SZ, D_SZ, D_SZ, 1.f,
                                                       MD, DD, MD, u3, vs, loglam_q, loglam_k);
            cur ^= 1;
        }
    }
    float* qf = ab[1];
    float* kf = ab[1] + MD;

    // 6) scores S = q k^T / 32, causal tiles skipped
    {
        dim3 g(T_SZ / BN, T_SZ / BM, B_SZ);
        mm_tf32<MODE_SCORE><<<g, thr, GSMEM_BYTES>>>(qf, kf, S, D_SZ, D_SZ, D_SZ, T_SZ, 0.03125f,
                                                     TD, TD, TT, nullptr, nullptr, nullptr, nullptr);
    }

    // 7) causal softmax (in place; rounds probs, zeroes masked tail)
    {
        dim3 g(T_SZ, B_SZ);
        softmax_causal<<<g, thr>>>(S);
    }

    // 8) o = P @ V (NT against Vt, causal K-limit); o tf32-rounded
    {
        dim3 g(D_SZ / BN, T_SZ / BM, B_SZ);
        mm_tf32<MODE_PV><<<g, thr, GSMEM_BYTES>>>(S, vt, o, T_SZ, T_SZ, T_SZ, D_SZ, 1.f,
                                                  TT, TD, TD, nullptr, nullptr, nullptr, nullptr);
    }

    // 9) out = o @ W_out^T (fp32 output)
    {
        dim3 g(D_SZ / BN, M_SZ / BM, 1);
        mm_tf32<MODE_PLAIN><<<g, thr, GSMEM_BYTES>>>(o, wor, out, D_SZ, D_SZ, D_SZ, D_SZ, 1.f,
                                                     0, 0, 0, nullptr, nullptr, nullptr, nullptr);
    }
}

// round 8
// speedup vs baseline: 1.3521x; 1.2083x over previous
#include <cuda_runtime.h>
#include <cstdint>
#include <math.h>

// ---------------- problem constants ----------------
#define B_SZ 4
#define T_SZ 2048
#define D_SZ 1024
#define M_SZ (B_SZ * T_SZ)
#define MD   ((long)M_SZ * D_SZ)
#define DD   ((long)D_SZ * D_SZ)
#define ETA_C 0.1f
#define LCA_GEMM_ITERS 9   // iteration 1 is fused into the QKV epilogue

// ---------------- scratch (device globals; no allocation) ----------------
__device__ float g_u3[3 * M_SZ * D_SZ];      // u_q, u_k, v (fp32; z-indexed)
__device__ float g_vt[M_SZ * D_SZ];          // V^T per batch [B][D][T] (tf32-rounded)
__device__ float g_vs[2 * M_SZ * D_SZ];      // LCA v-state (fp32)
__device__ float g_ab[2][2 * M_SZ * D_SZ];   // LCA codes ping-pong x (q,k) (tf32-rounded)
__device__ float g_G2[2 * D_SZ * D_SZ];      // sym zero-diag Gq,Gk (tf32-rounded)
__device__ float g_S[(size_t)B_SZ * T_SZ * T_SZ];   // scores / probs
__device__ float g_o[M_SZ * D_SZ];           // attention out (tf32-rounded)
__device__ float g_xr[M_SZ * D_SZ];          // x rounded
__device__ float g_wqkvr[3 * D_SZ * D_SZ];   // W_qkv rounded
__device__ float g_woutr[D_SZ * D_SZ];       // W_out rounded

// ---------------- helpers ----------------
__device__ __forceinline__ uint32_t smem_u32(const void* p) {
    uint32_t a;
    asm("{ .reg .u64 t; cvta.to.shared.u64 t, %1; cvt.u32.u64 %0, t; }" : "=r"(a) : "l"(p));
    return a;
}
__device__ __forceinline__ void cp_async16(uint32_t dst, const void* src) {
    asm volatile("cp.async.cg.shared.global [%0], [%1], 16;" :: "r"(dst), "l"(src));
}
#define CP_COMMIT() asm volatile("cp.async.commit_group;" ::: "memory")
#define CP_WAIT0()  asm volatile("cp.async.wait_group 0;" ::: "memory")

__device__ __forceinline__ uint32_t f2tf32(float f) {
    uint32_t r;
    asm("cvt.rna.tf32.f32 %0, %1;" : "=r"(r) : "f"(f));
    return r;
}
__device__ __forceinline__ float rtf(float f) { return __uint_as_float(f2tf32(f)); }

__device__ __forceinline__ void mma_tf32(float* c, const uint32_t* a, const uint32_t* b) {
    asm volatile(
        "mma.sync.aligned.m16n8k8.row.col.f32.tf32.tf32.f32 "
        "{%0,%1,%2,%3}, {%4,%5,%6,%7}, {%8,%9}, {%0,%1,%2,%3};"
        : "+f"(c[0]), "+f"(c[1]), "+f"(c[2]), "+f"(c[3])
        : "r"(a[0]), "r"(a[1]), "r"(a[2]), "r"(a[3]), "r"(b[0]), "r"(b[1]));
}

// ---------------- GEMM (NT): C[m,n] = alpha * sum_k A[m,k]*B[n,k] ----------------
// 128x128 CTA tile, 8 warps of 64x32, 2 CTAs/SM (proven R5 shape).
// 2-stage cp.async pipeline, ONE __syncthreads per chunk:
//   wait0 -> sync (frees buf (c-1)&1 == (c+1)&1) -> issue(c+1) -> compute(c)
// Inputs pre-rounded tf32; k-permuted layout for uint2 fragment loads.
#define MODE_QKV   0   // plain GEMM; for z<2 additionally writes vs=eta*u, a0=soft
#define MODE_LCA   1   // fused LCA prox epilogue (z: 0=q, 1=k); writes tf32-rounded a
#define MODE_SCORE 2   // triangular grid decode (blockIdx.x = linear lower-tri tile)
#define MODE_PV    3   // causal K-limit; writes tf32-rounded C
#define MODE_PLAIN 4   // plain GEMM with alpha

#define BK   32
#define STRD 40                       // floats per smem row (LDS.64 conflict-free)
#define TILE_SM (128 * STRD)
#define GSMEM_BYTES (4 * TILE_SM * 4) // 2 A + 2 B buffers = 81920 B

template <int MODE>
__global__ void __launch_bounds__(256, 2)
mm_tf32(const float* __restrict__ A, const float* __restrict__ Bm, float* __restrict__ C,
        int K, int ldA, int ldB, int ldC, float alpha,
        long sA, long sB, long sC,
        const float* __restrict__ U, float* __restrict__ Vst, float* __restrict__ Aux,
        const float* __restrict__ llq, const float* __restrict__ llk)
{
    int r0, c0;
    if (MODE == MODE_SCORE) {
        // decode linear lower-triangle tile index: t = by*(by+1)/2 + bx, bx<=by
        const int t = blockIdx.x;
        int by = (int)((sqrtf(8.f * t + 1.f) - 1.f) * 0.5f);
        while ((by + 1) * (by + 2) / 2 <= t) by++;
        while (by * (by + 1) / 2 > t) by--;
        const int bx = t - by * (by + 1) / 2;
        r0 = by * 128; c0 = bx * 128;
    } else {
        r0 = blockIdx.y * 128;
        c0 = blockIdx.x * 128;
    }

    const long bz = blockIdx.z;
    A  += bz * sA;
    Bm += bz * sB;
    C  += bz * sC;

    extern __shared__ uint32_t sm[];
    uint32_t* Asb[2] = { sm,               sm + TILE_SM };
    uint32_t* Bsb[2] = { sm + 2 * TILE_SM, sm + 3 * TILE_SM };

    const int tid  = threadIdx.x;
    const int lane = tid & 31;
    const int wid  = tid >> 5;
    const int wm   = (wid >> 2) * 64;
    const int wn   = (wid & 3) * 32;
    const int lr   = lane >> 2;         // 0..7
    const int lc   = lane & 3;          // 0..3

    const int kmax = (MODE == MODE_PV) ? min(K, r0 + 128) : K;
    const int nch  = kmax / BK;

    float acc[4][4][4];
#pragma unroll
    for (int i = 0; i < 4; i++)
#pragma unroll
        for (int j = 0; j < 4; j++)
#pragma unroll
            for (int e = 0; e < 4; e++) acc[i][j][e] = 0.f;

    auto issue = [&](int c) {
        const int buf = c & 1;
        const float* Ac = A  + (long)r0 * ldA + c * BK;
        const float* Bc = Bm + (long)c0 * ldB + c * BK;
        const uint32_t ab = smem_u32(Asb[buf]);
        const uint32_t bb = smem_u32(Bsb[buf]);
#pragma unroll
        for (int i = 0; i < 4; i++) {
            const int idx = tid + i * 256;
            const int row = idx >> 3, c4 = idx & 7;
            cp_async16(ab + (uint32_t)(row * STRD + c4 * 4) * 4, Ac + (long)row * ldA + c4 * 4);
            cp_async16(bb + (uint32_t)(row * STRD + c4 * 4) * 4, Bc + (long)row * ldB + c4 * 4);
        }
        CP_COMMIT();
    };

    issue(0);
    for (int c = 0; c < nch; c++) {
        CP_WAIT0();                 // chunk c landed (only group outstanding)
        __syncthreads();            // all warps done reading buf (c-1)&1 == (c+1)&1
        if (c + 1 < nch) issue(c + 1);

        const uint32_t* Ab = Asb[c & 1];
        const uint32_t* Bb = Bsb[c & 1];
#pragma unroll
        for (int o = 0; o < 4; o++) {
            const int koff = o * 8 + lc * 2;
            uint32_t af[4][4], bf[4][2];
#pragma unroll
            for (int mt = 0; mt < 4; mt++) {
                const uint2 lo = *(const uint2*)(Ab + (wm + mt * 16 + lr) * STRD + koff);
                const uint2 hi = *(const uint2*)(Ab + (wm + mt * 16 + lr + 8) * STRD + koff);
                af[mt][0] = lo.x;  af[mt][2] = lo.y;
                af[mt][1] = hi.x;  af[mt][3] = hi.y;
            }
#pragma unroll
            for (int nt = 0; nt < 4; nt++) {
                const uint2 bv = *(const uint2*)(Bb + (wn + nt * 8 + lr) * STRD + koff);
                bf[nt][0] = bv.x;  bf[nt][1] = bv.y;
            }
#pragma unroll
            for (int mt = 0; mt < 4; mt++)
#pragma unroll
                for (int nt = 0; nt < 4; nt++)
                    mma_tf32(acc[mt][nt], af[mt], bf[nt]);
        }
    }

    // ---------------- epilogue ----------------
    float lam = 0.f;
    if (MODE == MODE_LCA || (MODE == MODE_QKV && bz < 2))
        lam = expf(bz == 0 ? *llq : *llk);
#pragma unroll
    for (int mt = 0; mt < 4; mt++) {
#pragma unroll
        for (int h = 0; h < 2; h++) {
            const int row = r0 + wm + mt * 16 + lr + h * 8;
#pragma unroll
            for (int nt = 0; nt < 4; nt++) {
                const int col = c0 + wn + nt * 8 + lc * 2;
                const long idx = (long)row * ldC + col;
                float x0 = acc[mt][nt][h * 2 + 0];
                float x1 = acc[mt][nt][h * 2 + 1];
                if (MODE == MODE_LCA) {
                    float2 u2 = *(const float2*)(U + bz * sC + idx);
                    float2 v2 = *(const float2*)(Vst + bz * sC + idx);
                    float2 vn, o2;
                    vn.x = v2.x + ETA_C * (u2.x - v2.x - x0);
                    vn.y = v2.y + ETA_C * (u2.y - v2.y - x1);
                    *(float2*)(Vst + bz * sC + idx) = vn;
                    float s;
                    s = fabsf(vn.x) - lam; o2.x = (s > 0.f) ? rtf(copysignf(s, vn.x)) : 0.f;
                    s = fabsf(vn.y) - lam; o2.y = (s > 0.f) ? rtf(copysignf(s, vn.y)) : 0.f;
                    *(float2*)(C + idx) = o2;
                } else if (MODE == MODE_QKV) {
                    *(float2*)(C + idx) = make_float2(x0, x1);       // u (fp32)
                    if (bz < 2) {                                    // fused LCA iter 1
                        float2 vn = make_float2(ETA_C * x0, ETA_C * x1);
                        *(float2*)(Vst + bz * sC + idx) = vn;
                        float s; float2 a2;
                        s = fabsf(vn.x) - lam; a2.x = (s > 0.f) ? rtf(copysignf(s, vn.x)) : 0.f;
                        s = fabsf(vn.y) - lam; a2.y = (s > 0.f) ? rtf(copysignf(s, vn.y)) : 0.f;
                        *(float2*)(Aux + bz * sC + idx) = a2;
                    }
                } else if (MODE == MODE_PV) {
                    *(float2*)(C + idx) = make_float2(rtf(x0), rtf(x1));   // feeds final GEMM
                } else {                                              // SCORE / PLAIN
                    *(float2*)(C + idx) = make_float2(alpha * x0, alpha * x1);
                }
            }
        }
    }
}

// ---------------- small kernels ----------------
__global__ void round_copy(const float* __restrict__ in, float* __restrict__ out)
{
    const long i = ((long)blockIdx.x * blockDim.x + threadIdx.x) * 4;
    float4 v = *(const float4*)(in + i);
    v.x = rtf(v.x); v.y = rtf(v.y); v.z = rtf(v.z); v.w = rtf(v.w);
    *(float4*)(out + i) = v;
}

// both G matrices in one launch (z selects)
__global__ void symzero2(const float* __restrict__ Gq, const float* __restrict__ Gk,
                         float* __restrict__ Gs)
{
    const long idx = (long)blockIdx.x * blockDim.x + threadIdx.x;
    const long e = idx & (DD - 1);
    const float* G = (idx < DD) ? Gq : Gk;
    const int i = (int)(e / D_SZ), j = (int)(e % D_SZ);
    Gs[idx] = (i == j) ? 0.f : rtf(0.5f * (G[e] + G[(long)j * D_SZ + i]));
}

// V [B][T][D] -> Vt [B][D][T], tf32-rounded
__global__ void transpose_bt(const float* __restrict__ in, float* __restrict__ out)
{
    __shared__ float t[32][33];
    const int b = blockIdx.z;
    const int t0 = blockIdx.x * 32, d0 = blockIdx.y * 32;
    in  += (long)b * T_SZ * D_SZ;
    out += (long)b * T_SZ * D_SZ;
    const int x = threadIdx.x, y = threadIdx.y;
#pragma unroll
    for (int i = 0; i < 32; i += 8)
        t[y + i][x] = in[(long)(t0 + y + i) * D_SZ + d0 + x];
    __syncthreads();
#pragma unroll
    for (int i = 0; i < 32; i += 8)
        out[(long)(d0 + y + i) * T_SZ + t0 + x] = rtf(t[x][y + i]);
}

__global__ void softmax_causal(float* __restrict__ S)
{
    const int i = blockIdx.x;
    const int b = blockIdx.y;
    float* row = S + ((long)b * T_SZ + i) * T_SZ;
    const int tid = threadIdx.x;
    const int n = i + 1;
    __shared__ float red[256];

    float mx = -INFINITY;
    for (int j = tid; j < n; j += 256) mx = fmaxf(mx, row[j]);
    red[tid] = mx;
    __syncthreads();
    for (int s = 128; s > 0; s >>= 1) {
        if (tid < s) red[tid] = fmaxf(red[tid], red[tid + s]);
        __syncthreads();
    }
    mx = red[0];
    __syncthreads();

    float sum = 0.f;
    for (int j = tid; j < n; j += 256) {
        float e = expf(row[j] - mx);
        row[j] = e;
        sum += e;
    }
    red[tid] = sum;
    __syncthreads();
    for (int s = 128; s > 0; s >>= 1) {
        if (tid < s) red[tid] += red[tid + s];
        __syncthreads();
    }
    const float inv = 1.f / red[0];
    for (int j = tid; j < n; j += 256) row[j] = rtf(row[j] * inv);   // feeds PV GEMM
    for (int j = n + tid; j < T_SZ; j += 256) row[j] = 0.f;
}

// ---------------- launch ----------------
extern "C" void kernel_launch(void* const* d_in, const int* in_sizes, int n_in,
                              void* d_out, int out_size)
{
    const float* x        = (const float*)d_in[0];
    const float* W_qkv    = (const float*)d_in[1];
    const float* W_out    = (const float*)d_in[2];
    const float* Gq_raw   = (const float*)d_in[3];
    const float* loglam_q = (const float*)d_in[4];
    const float* Gk_raw   = (const float*)d_in[5];
    const float* loglam_k = (const float*)d_in[6];
    float* out = (float*)d_out;
    (void)in_sizes; (void)n_in; (void)out_size;

    float *u3, *vt, *vs, *abb, *G2, *S, *o, *xr, *wqr, *wor;
    cudaGetSymbolAddress((void**)&u3,  g_u3);
    cudaGetSymbolAddress((void**)&vt,  g_vt);
    cudaGetSymbolAddress((void**)&vs,  g_vs);
    cudaGetSymbolAddress((void**)&abb, g_ab);
    cudaGetSymbolAddress((void**)&G2,  g_G2);
    cudaGetSymbolAddress((void**)&S,   g_S);
    cudaGetSymbolAddress((void**)&o,   g_o);
    cudaGetSymbolAddress((void**)&xr,  g_xr);
    cudaGetSymbolAddress((void**)&wqr, g_wqkvr);
    cudaGetSymbolAddress((void**)&wor, g_woutr);

    cudaFuncSetAttribute(mm_tf32<MODE_QKV>,   cudaFuncAttributeMaxDynamicSharedMemorySize, GSMEM_BYTES);
    cudaFuncSetAttribute(mm_tf32<MODE_LCA>,   cudaFuncAttributeMaxDynamicSharedMemorySize, GSMEM_BYTES);
    cudaFuncSetAttribute(mm_tf32<MODE_SCORE>, cudaFuncAttributeMaxDynamicSharedMemorySize, GSMEM_BYTES);
    cudaFuncSetAttribute(mm_tf32<MODE_PV>,    cudaFuncAttributeMaxDynamicSharedMemorySize, GSMEM_BYTES);
    cudaFuncSetAttribute(mm_tf32<MODE_PLAIN>, cudaFuncAttributeMaxDynamicSharedMemorySize, GSMEM_BYTES);

    float* ab[2] = { abb, abb + 2 * MD };
    float* vvv = u3 + 2 * MD;

    const dim3 thr(256);
    const long TD = (long)T_SZ * D_SZ;
    const long TT = (long)T_SZ * T_SZ;

    // 0) pre-round raw GEMM inputs to tf32
    round_copy<<<(unsigned)(MD / 1024), thr>>>(x, xr);
    round_copy<<<(unsigned)(3 * DD / 1024), thr>>>(W_qkv, wqr);
    round_copy<<<(unsigned)(DD / 1024), thr>>>(W_out, wor);

    // 1) symmetrize + zero-diag both G's (tf32-rounded), one launch
    symzero2<<<(unsigned)(2 * DD / 256), thr>>>(Gq_raw, Gk_raw, G2);

    // 2) QKV projections + fused LCA iteration 1 (z<2 writes vs, a0)
    {
        dim3 g(D_SZ / 128, M_SZ / 128, 3);
        mm_tf32<MODE_QKV><<<g, thr, GSMEM_BYTES>>>(xr, wqr, u3, D_SZ, D_SZ, D_SZ, D_SZ, 1.f,
                                                   0, DD, MD, nullptr, vs, ab[0],
                                                   loglam_q, loglam_k);
    }

    // 3) transpose V (tf32-rounded)
    {
        dim3 g(T_SZ / 32, D_SZ / 32, B_SZ);
        transpose_bt<<<g, dim3(32, 8)>>>(vvv, vt);
    }

    // 4) LCA iterations 2..10: fused a@G + prox, q+k merged over z
    {
        dim3 g(D_SZ / 128, M_SZ / 128, 2);
        int cur = 0;
        for (int it = 0; it < LCA_GEMM_ITERS; it++) {
            mm_tf32<MODE_LCA><<<g, thr, GSMEM_BYTES>>>(ab[cur], G2, ab[cur ^ 1],
                                                       D_SZ, D_SZ, D_SZ, D_SZ, 1.f,
                                                       MD, DD, MD, u3, vs, nullptr,
                                                       loglam_q, loglam_k);
            cur ^= 1;
        }
    }
    float* qf = ab[1];
    float* kf = ab[1] + MD;

    // 5) scores S = q k^T / 32, triangular grid (136 live tiles x batch)
    {
        dim3 g(136, 1, B_SZ);
        mm_tf32<MODE_SCORE><<<g, thr, GSMEM_BYTES>>>(qf, kf, S, D_SZ, D_SZ, D_SZ, T_SZ, 0.03125f,
                                                     TD, TD, TT, nullptr, nullptr, nullptr,
                                                     nullptr, nullptr);
    }

    // 6) causal softmax (in place; rounds probs, zeroes masked tail)
    {
        dim3 g(T_SZ, B_SZ);
        softmax_causal<<<g, thr>>>(S);
    }

    // 7) o = P @ V (NT against Vt, causal K-limit); o tf32-rounded
    {
        dim3 g(D_SZ / 128, T_SZ / 128, B_SZ);
        mm_tf32<MODE_PV><<<g, thr, GSMEM_BYTES>>>(S, vt, o, T_SZ, T_SZ, T_SZ, D_SZ, 1.f,
                                                  TT, TD, TD, nullptr, nullptr, nullptr,
                                                  nullptr, nullptr);
    }

    // 8) out = o @ W_out^T (fp32 output)
    {
        dim3 g(D_SZ / 128, M_SZ / 128, 1);
        mm_tf32<MODE_PLAIN><<<g, thr, GSMEM_BYTES>>>(o, wor, out, D_SZ, D_SZ, D_SZ, D_SZ, 1.f,
                                                     0, 0, 0, nullptr, nullptr, nullptr,
                                                     nullptr, nullptr);
    }
}